// round 13
// baseline (speedup 1.0000x reference)
#include <cuda_runtime.h>
#include <cuda_fp16.h>
#include <climits>

#define BB 4
#define NN 65536
#define HH 128
#define WW 128
#define C_ALL 448   // 64 + 128 + 256

// fused NHWC fp16 scratch [b][y][x][448], 56 MB
__device__ __half g_t[(size_t)BB * HH * WW * C_ALL];
__device__ float  g_grid0[BB * NN];
__device__ float  g_grid1[BB * NN];
// bbox sentinels: statically initialized; re-armed by sample_kernel each run
// (sample never reads bbox, so the reset is safely ordered for the NEXT run).
__device__ int g_bbox[BB][4] = {
    {INT_MAX, INT_MAX, INT_MIN, INT_MIN}, {INT_MAX, INT_MAX, INT_MIN, INT_MIN},
    {INT_MAX, INT_MAX, INT_MIN, INT_MIN}, {INT_MAX, INT_MAX, INT_MIN, INT_MIN}};

// ---------------------------------------------------------------------------
__device__ __forceinline__ void point_coords(float gx, float gy,
                                             int& x0, int& x1, int& y0, int& y1,
                                             float& wx, float& wy) {
    float ix = ((gx + 1.0f) * 128.0f - 1.0f) * 0.5f;
    float iy = ((gy + 1.0f) * 128.0f - 1.0f) * 0.5f;
    ix = fminf(fmaxf(ix, 0.0f), 127.0f);
    iy = fminf(fmaxf(iy, 0.0f), 127.0f);
    float fx0 = floorf(ix), fy0 = floorf(iy);
    wx = ix - fx0; wy = iy - fy0;
    x0 = (int)fx0; y0 = (int)fy0;
    x1 = min(x0 + 1, 127); y1 = min(y0 + 1, 127);
}

// Block-wide bbox reduce; 512-thread block, all threads same batch b.
__device__ __forceinline__ void bbox_reduce(int b, int x0, int y0,
                                            int x1, int y1) {
    __shared__ int sm[4][16];
    int mnx = __reduce_min_sync(0xffffffffu, x0);
    int mny = __reduce_min_sync(0xffffffffu, y0);
    int mxx = __reduce_max_sync(0xffffffffu, x1);
    int mxy = __reduce_max_sync(0xffffffffu, y1);
    int w = threadIdx.x >> 5;
    if ((threadIdx.x & 31) == 0) {
        sm[0][w] = mnx; sm[1][w] = mny; sm[2][w] = mxx; sm[3][w] = mxy;
    }
    __syncthreads();
    if (threadIdx.x == 0) {
        int a0 = sm[0][0], a1 = sm[1][0], a2 = sm[2][0], a3 = sm[3][0];
#pragma unroll
        for (int i = 1; i < 16; i++) {
            a0 = min(a0, sm[0][i]); a1 = min(a1, sm[1][i]);
            a2 = max(a2, sm[2][i]); a3 = max(a3, sm[3][i]);
        }
        atomicMin(&g_bbox[b][0], a0); atomicMin(&g_bbox[b][1], a1);
        atomicMax(&g_bbox[b][2], a2); atomicMax(&g_bbox[b][3], a3);
    }
}

// ---------------------------------------------------------------------------
// Base grid + fused bbox. 512 blocks x 512 threads; block spans one batch.
// ---------------------------------------------------------------------------
__global__ void __launch_bounds__(512) base_grid_kernel(
        const float* __restrict__ x_loc, const float* __restrict__ Wr,
        const float* __restrict__ br) {
    int idx = blockIdx.x * 512 + threadIdx.x;
    int b = idx >> 16, n = idx & (NN - 1);
    float x0v = x_loc[(b * 3 + 0) * NN + n];
    float x1v = x_loc[(b * 3 + 1) * NN + n];
    float x2v = x_loc[(b * 3 + 2) * NN + n];
    float g0 = br[0] + Wr[0] * x0v + Wr[1] * x1v + Wr[2] * x2v;
    float g1 = br[1] + Wr[131] * x0v + Wr[132] * x1v + Wr[133] * x2v;
    g_grid0[idx] = g0;
    g_grid1[idx] = g1;
    int x0, x1, y0, y1; float wx, wy;
    point_coords(g0, g1, x0, x1, y0, y1, wx, wy);
    bbox_reduce(b, x0, y0, x1, y1);
}

// ---------------------------------------------------------------------------
// Fallback MLP path. Each block first checks (from L2) whether Wr touches
// the MLP features at all; early-exits when not (the benched case). When
// active it grows the bbox; bbox only accumulates so the union is safe.
// ---------------------------------------------------------------------------
__global__ void __launch_bounds__(512) mlp_grid_kernel(
        const float* __restrict__ x_loc, const float* __restrict__ x_feat,
        const float* __restrict__ W1, const float* __restrict__ b1,
        const float* __restrict__ W2, const float* __restrict__ b2,
        const float* __restrict__ Wr) {
    {
        int t = threadIdx.x, nz = 0;
        if (t < 262) {
            int row = t / 131, k = t % 131;
            if (k >= 3 && Wr[row * 131 + k] != 0.0f) nz = 1;
        }
        if (__syncthreads_or(nz) == 0) return;
    }
    int idx = blockIdx.x * 512 + threadIdx.x;
    int b = idx >> 16, n = idx & (NN - 1);

    float x[67];
    for (int k = 0; k < 3; k++)  x[k] = x_loc[(b * 3 + k) * NN + n];
    for (int k = 0; k < 64; k++) x[3 + k] = x_feat[(b * 64 + k) * NN + n];
    float h1[128];
    for (int j = 0; j < 128; j++) {
        float s = b1[j];
        for (int k = 0; k < 67; k++) s += W1[j * 67 + k] * x[k];
        h1[j] = fmaxf(s, 0.0f);
    }
    float g0 = 0.0f, g1 = 0.0f;
    for (int j = 0; j < 128; j++) {
        float s = b2[j];
        for (int k = 0; k < 128; k++) s += W2[j * 128 + k] * h1[k];
        s = fmaxf(s, 0.0f);
        g0 += Wr[3 + j] * s;
        g1 += Wr[131 + 3 + j] * s;
    }
    g0 += g_grid0[idx];
    g1 += g_grid1[idx];
    g_grid0[idx] = g0;
    g_grid1[idx] = g1;
    int x0, x1, y0, y1; float wx, wy;
    point_coords(g0, g1, x0, x1, y0, y1, wx, wy);
    bbox_reduce(b, x0, y0, x1, y1);
}

// ---------------------------------------------------------------------------
// bbox-gated transpose to flat NHWC fp16. grid (4, 7, 256), block = 256
// FLAT threads. TWO y rows, 32 x's, one 64-channel tile per block. Loads
// are 4x LDG.128 per thread; warp stores 64 contiguous fp16 (128 B)/texel.
// ---------------------------------------------------------------------------
__global__ void __launch_bounds__(256) transpose_kernel(
        const float* __restrict__ m0, const float* __restrict__ m1,
        const float* __restrict__ m2) {
    int b  = blockIdx.z >> 6;
    int yb = (blockIdx.z & 63) << 1;
    int xt = blockIdx.x << 5;
    int bx0 = g_bbox[b][0], bx1 = g_bbox[b][2];
    int by0 = g_bbox[b][1], by1 = g_bbox[b][3];
    if (yb + 1 < by0 || yb > by1 || xt > bx1 || xt + 31 < bx0) return;

    int ct = blockIdx.y;                   // 7 tiles of 64 channels
    const float* m; int C, c0, coff;
    if (ct == 0)      { m = m0; C = 64;  c0 = 0;             coff = 0; }
    else if (ct < 3)  { m = m1; C = 128; c0 = (ct - 1) * 64; coff = 64 + c0; }
    else              { m = m2; C = 256; c0 = (ct - 3) * 64; coff = 192 + c0; }

    __shared__ float tile[2][64][33];
    int tid = threadIdx.x;                 // FLAT 0..255
    // 1024 16B granules: g -> (q = x-quad, c, yy); consecutive tid = coalesced
#pragma unroll
    for (int i = 0; i < 4; i++) {
        int g = tid + i * 256;
        int q = g & 7, c = (g >> 3) & 63, yy = g >> 9;
        float4 v = *(const float4*)(m + ((size_t)(b * C + c0 + c) * HH + yb + yy) * WW + xt + q * 4);
        float* dst = &tile[yy][c][q * 4];
        dst[0] = v.x; dst[1] = v.y; dst[2] = v.z; dst[3] = v.w;
    }
    __syncthreads();

    // warp w handles x = xt + 4w .. 4w+3; lane = channel pair -> 128 B store
    int w = tid >> 5, lane = tid & 31;
#pragma unroll
    for (int yy = 0; yy < 2; yy++)
#pragma unroll
        for (int xi = 0; xi < 4; xi++) {
            int x = (w << 2) + xi;
            __half2 h = __floats2half2_rn(tile[yy][2 * lane][x], tile[yy][2 * lane + 1][x]);
            *(__half2*)&g_t[((size_t)((b * HH + yb + yy) * WW + xt + x)) * C_ALL + coff + 2 * lane] = h;
        }
}

// ---------------------------------------------------------------------------
// Bilinear gather + channel transpose. 64 points/block, 512 threads.
// Warp handles 4 points: lane>>3 = point-sub, lane&7 = channel octet.
// Each lane loads float4 (8 fp16) per texel row -> LDG.128, 512 B/warp.
// Staging is an XOR-swizzled float4 array: quad (p, cq) lives at
// val4[p*16 + (cq ^ (p&15))] -> both STS.128 and LDS.128 run at the
// 128 B/cycle crossbar minimum (no conflicts). Double-buffered so
// gather(c+1) overlaps write(c). Block (0,0) re-arms bbox sentinels.
// ---------------------------------------------------------------------------
__global__ void __launch_bounds__(512) sample_kernel(float* __restrict__ out) {
    __shared__ float  s_w[4][64];
    __shared__ int    s_base[4][64];
    __shared__ float4 val4[2][64 * 16];    // 32 KB

    int b   = blockIdx.y;
    int n0  = blockIdx.x << 6;
    int tid = threadIdx.x;
    int lane = tid & 31, w = tid >> 5;

    if (blockIdx.x == 0 && blockIdx.y == 0 && tid < 16)
        ((int*)g_bbox)[tid] = ((tid & 3) < 2) ? INT_MAX : INT_MIN;

    if (tid < 64) {
        int idx = b * NN + n0 + tid;
        int x0, x1, y0, y1; float wx, wy;
        point_coords(g_grid0[idx], g_grid1[idx], x0, x1, y0, y1, wx, wy);
        s_w[0][tid] = (1.0f - wy) * (1.0f - wx);
        s_w[1][tid] = (1.0f - wy) * wx;
        s_w[2][tid] = wy * (1.0f - wx);
        s_w[3][tid] = wy * wx;
        int r0 = (b * HH + y0) * WW;
        int r1 = (b * HH + y1) * WW;
        s_base[0][tid] = (r0 + x0) * C_ALL;
        s_base[1][tid] = (r0 + x1) * C_ALL;
        s_base[2][tid] = (r1 + x0) * C_ALL;
        s_base[3][tid] = (r1 + x1) * C_ALL;
    }
    __syncthreads();

    int p   = (w << 2) + (lane >> 3);   // this lane's point (0..63)
    int oct = lane & 7;                 // channel octet within 64-ch chunk
    int psw = p & 15;                   // staging swizzle key
    float pw[4];
    int   pb_[4];
#pragma unroll
    for (int t = 0; t < 4; t++) { pw[t] = s_w[t][p]; pb_[t] = s_base[t][p]; }

    auto gather = [&](int chunk, int buf) {
        int cc = chunk * 64 + (oct << 3);
        float r[8] = {0.f, 0.f, 0.f, 0.f, 0.f, 0.f, 0.f, 0.f};
#pragma unroll
        for (int t = 0; t < 4; t++) {
            uint4 u = *(const uint4*)&g_t[pb_[t] + cc];
            float wt = pw[t];
#pragma unroll
            for (int k = 0; k < 4; k++) {
                float2 f = __half22float2(((const __half2*)&u)[k]);
                r[2 * k]     += wt * f.x;
                r[2 * k + 1] += wt * f.y;
            }
        }
        val4[buf][p * 16 + ((oct * 2)     ^ psw)] = make_float4(r[0], r[1], r[2], r[3]);
        val4[buf][p * 16 + ((oct * 2 + 1) ^ psw)] = make_float4(r[4], r[5], r[6], r[7]);
    };

    gather(0, 0);
    __syncthreads();

#pragma unroll
    for (int chunk = 0; chunk < 7; chunk++) {
        int buf = chunk & 1;
        if (chunk + 1 < 7) gather(chunk + 1, buf ^ 1);

        // write: warp w owns channel quad w (c0+4w..4w+3); lane = point n
        int c0 = chunk * 64;
        float* outp = out + ((size_t)(b * C_ALL + c0 + (w << 2))) * NN + n0;
#pragma unroll
        for (int it = 0; it < 2; it++) {
            int n = it * 32 + lane;
            float4 v = val4[buf][n * 16 + (w ^ (n & 15))];
            __stcs(&outp[0 * NN + n], v.x);
            __stcs(&outp[1 * NN + n], v.y);
            __stcs(&outp[2 * NN + n], v.z);
            __stcs(&outp[3 * NN + n], v.w);
        }
        __syncthreads();
    }
}

// ---------------------------------------------------------------------------
extern "C" void kernel_launch(void* const* d_in, const int* in_sizes, int n_in,
                              void* d_out, int out_size) {
    const float* x_loc  = (const float*)d_in[0];
    const float* x_feat = (const float*)d_in[1];
    const float* m0     = (const float*)d_in[2];
    const float* m1     = (const float*)d_in[3];
    const float* m2     = (const float*)d_in[4];
    const float* W1     = (const float*)d_in[5];
    const float* b1     = (const float*)d_in[6];
    const float* W2     = (const float*)d_in[7];
    const float* b2     = (const float*)d_in[8];
    const float* Wr     = (const float*)d_in[9];
    const float* br     = (const float*)d_in[10];
    float* out = (float*)d_out;

    base_grid_kernel<<<512, 512>>>(x_loc, Wr, br);
    mlp_grid_kernel<<<512, 512>>>(x_loc, x_feat, W1, b1, W2, b2, Wr);
    transpose_kernel<<<dim3(4, 7, 256), 256>>>(m0, m1, m2);
    sample_kernel<<<dim3(NN / 64, BB), 512>>>(out);
}

// round 14
// speedup vs baseline: 1.0781x; 1.0781x over previous
#include <cuda_runtime.h>
#include <cuda_fp16.h>
#include <climits>

#define BB 4
#define NN 65536
#define HH 128
#define WW 128
#define C_ALL 448   // 64 + 128 + 256
#define VST 69      // staging stride: odd (conflict-free loads) + room for +4 octet offset

// fused NHWC fp16 scratch [b][y][x][448], 56 MB
__device__ __half g_t[(size_t)BB * HH * WW * C_ALL];
__device__ float  g_grid0[BB * NN];
__device__ float  g_grid1[BB * NN];
// bbox sentinels: statically initialized; re-armed by sample_kernel each run
// (sample never reads bbox, so the reset is safely ordered for the NEXT run).
__device__ int g_bbox[BB][4] = {
    {INT_MAX, INT_MAX, INT_MIN, INT_MIN}, {INT_MAX, INT_MAX, INT_MIN, INT_MIN},
    {INT_MAX, INT_MAX, INT_MIN, INT_MIN}, {INT_MAX, INT_MAX, INT_MIN, INT_MIN}};

// ---------------------------------------------------------------------------
__device__ __forceinline__ void point_coords(float gx, float gy,
                                             int& x0, int& x1, int& y0, int& y1,
                                             float& wx, float& wy) {
    float ix = ((gx + 1.0f) * 128.0f - 1.0f) * 0.5f;
    float iy = ((gy + 1.0f) * 128.0f - 1.0f) * 0.5f;
    ix = fminf(fmaxf(ix, 0.0f), 127.0f);
    iy = fminf(fmaxf(iy, 0.0f), 127.0f);
    float fx0 = floorf(ix), fy0 = floorf(iy);
    wx = ix - fx0; wy = iy - fy0;
    x0 = (int)fx0; y0 = (int)fy0;
    x1 = min(x0 + 1, 127); y1 = min(y0 + 1, 127);
}

// Block-wide bbox reduce; 512-thread block, all threads same batch b.
__device__ __forceinline__ void bbox_reduce(int b, int x0, int y0,
                                            int x1, int y1) {
    __shared__ int sm[4][16];
    int mnx = __reduce_min_sync(0xffffffffu, x0);
    int mny = __reduce_min_sync(0xffffffffu, y0);
    int mxx = __reduce_max_sync(0xffffffffu, x1);
    int mxy = __reduce_max_sync(0xffffffffu, y1);
    int w = threadIdx.x >> 5;
    if ((threadIdx.x & 31) == 0) {
        sm[0][w] = mnx; sm[1][w] = mny; sm[2][w] = mxx; sm[3][w] = mxy;
    }
    __syncthreads();
    if (threadIdx.x == 0) {
        int a0 = sm[0][0], a1 = sm[1][0], a2 = sm[2][0], a3 = sm[3][0];
#pragma unroll
        for (int i = 1; i < 16; i++) {
            a0 = min(a0, sm[0][i]); a1 = min(a1, sm[1][i]);
            a2 = max(a2, sm[2][i]); a3 = max(a3, sm[3][i]);
        }
        atomicMin(&g_bbox[b][0], a0); atomicMin(&g_bbox[b][1], a1);
        atomicMax(&g_bbox[b][2], a2); atomicMax(&g_bbox[b][3], a3);
    }
}

// ---------------------------------------------------------------------------
// Base grid + fused bbox. 512 blocks x 512 threads; block spans one batch.
// ---------------------------------------------------------------------------
__global__ void __launch_bounds__(512) base_grid_kernel(
        const float* __restrict__ x_loc, const float* __restrict__ Wr,
        const float* __restrict__ br) {
    int idx = blockIdx.x * 512 + threadIdx.x;
    int b = idx >> 16, n = idx & (NN - 1);
    float x0v = x_loc[(b * 3 + 0) * NN + n];
    float x1v = x_loc[(b * 3 + 1) * NN + n];
    float x2v = x_loc[(b * 3 + 2) * NN + n];
    float g0 = br[0] + Wr[0] * x0v + Wr[1] * x1v + Wr[2] * x2v;
    float g1 = br[1] + Wr[131] * x0v + Wr[132] * x1v + Wr[133] * x2v;
    g_grid0[idx] = g0;
    g_grid1[idx] = g1;
    int x0, x1, y0, y1; float wx, wy;
    point_coords(g0, g1, x0, x1, y0, y1, wx, wy);
    bbox_reduce(b, x0, y0, x1, y1);
}

// ---------------------------------------------------------------------------
// Fallback MLP path. Each block first checks (from L2) whether Wr touches
// the MLP features at all; early-exits when not (the benched case). When
// active it grows the bbox; bbox only accumulates so the union is safe.
// ---------------------------------------------------------------------------
__global__ void __launch_bounds__(512) mlp_grid_kernel(
        const float* __restrict__ x_loc, const float* __restrict__ x_feat,
        const float* __restrict__ W1, const float* __restrict__ b1,
        const float* __restrict__ W2, const float* __restrict__ b2,
        const float* __restrict__ Wr) {
    {
        int t = threadIdx.x, nz = 0;
        if (t < 262) {
            int row = t / 131, k = t % 131;
            if (k >= 3 && Wr[row * 131 + k] != 0.0f) nz = 1;
        }
        if (__syncthreads_or(nz) == 0) return;
    }
    int idx = blockIdx.x * 512 + threadIdx.x;
    int b = idx >> 16, n = idx & (NN - 1);

    float x[67];
    for (int k = 0; k < 3; k++)  x[k] = x_loc[(b * 3 + k) * NN + n];
    for (int k = 0; k < 64; k++) x[3 + k] = x_feat[(b * 64 + k) * NN + n];
    float h1[128];
    for (int j = 0; j < 128; j++) {
        float s = b1[j];
        for (int k = 0; k < 67; k++) s += W1[j * 67 + k] * x[k];
        h1[j] = fmaxf(s, 0.0f);
    }
    float g0 = 0.0f, g1 = 0.0f;
    for (int j = 0; j < 128; j++) {
        float s = b2[j];
        for (int k = 0; k < 128; k++) s += W2[j * 128 + k] * h1[k];
        s = fmaxf(s, 0.0f);
        g0 += Wr[3 + j] * s;
        g1 += Wr[131 + 3 + j] * s;
    }
    g0 += g_grid0[idx];
    g1 += g_grid1[idx];
    g_grid0[idx] = g0;
    g_grid1[idx] = g1;
    int x0, x1, y0, y1; float wx, wy;
    point_coords(g0, g1, x0, x1, y0, y1, wx, wy);
    bbox_reduce(b, x0, y0, x1, y1);
}

// ---------------------------------------------------------------------------
// bbox-gated transpose to flat NHWC fp16. grid (4, 7, 256), block = 256
// FLAT threads. TWO y rows, 32 x's, one 64-channel tile per block. Loads
// are 4x LDG.128 per thread; warp stores 64 contiguous fp16 (128 B)/texel.
// ---------------------------------------------------------------------------
__global__ void __launch_bounds__(256) transpose_kernel(
        const float* __restrict__ m0, const float* __restrict__ m1,
        const float* __restrict__ m2) {
    int b  = blockIdx.z >> 6;
    int yb = (blockIdx.z & 63) << 1;
    int xt = blockIdx.x << 5;
    int bx0 = g_bbox[b][0], bx1 = g_bbox[b][2];
    int by0 = g_bbox[b][1], by1 = g_bbox[b][3];
    if (yb + 1 < by0 || yb > by1 || xt > bx1 || xt + 31 < bx0) return;

    int ct = blockIdx.y;                   // 7 tiles of 64 channels
    const float* m; int C, c0, coff;
    if (ct == 0)      { m = m0; C = 64;  c0 = 0;             coff = 0; }
    else if (ct < 3)  { m = m1; C = 128; c0 = (ct - 1) * 64; coff = 64 + c0; }
    else              { m = m2; C = 256; c0 = (ct - 3) * 64; coff = 192 + c0; }

    __shared__ float tile[2][64][33];
    int tid = threadIdx.x;                 // FLAT 0..255
    // 1024 16B granules: g -> (q = x-quad, c, yy); consecutive tid = coalesced
#pragma unroll
    for (int i = 0; i < 4; i++) {
        int g = tid + i * 256;
        int q = g & 7, c = (g >> 3) & 63, yy = g >> 9;
        float4 v = *(const float4*)(m + ((size_t)(b * C + c0 + c) * HH + yb + yy) * WW + xt + q * 4);
        float* dst = &tile[yy][c][q * 4];
        dst[0] = v.x; dst[1] = v.y; dst[2] = v.z; dst[3] = v.w;
    }
    __syncthreads();

    // warp w handles x = xt + 4w .. 4w+3; lane = channel pair -> 128 B store
    int w = tid >> 5, lane = tid & 31;
#pragma unroll
    for (int yy = 0; yy < 2; yy++)
#pragma unroll
        for (int xi = 0; xi < 4; xi++) {
            int x = (w << 2) + xi;
            __half2 h = __floats2half2_rn(tile[yy][2 * lane][x], tile[yy][2 * lane + 1][x]);
            *(__half2*)&g_t[((size_t)((b * HH + yb + yy) * WW + xt + x)) * C_ALL + coff + 2 * lane] = h;
        }
}

// ---------------------------------------------------------------------------
// Bilinear gather + channel transpose. 64 points/block, 512 threads.
// Warp handles 4 points: lane>>3 = point-sub, lane&7 = channel octet.
// Each lane loads float4 (8 fp16) per texel row -> LDG.128, 512 B/warp.
// Staging: scalar ops (max ILP) with CONFLICT-FREE addressing:
//   index = p*69 + oct*8 + k + (oct>>2)*4
//   stores: bank = 5p + 8(oct&3) + 4(oct>>2) + k -> injective over warp
//   loads:  bank = 5n + const (5 coprime 32)     -> conflict-free
// Double-buffered so gather(c+1) overlaps write(c). Block (0,0) re-arms
// bbox sentinels for the next replay.
// ---------------------------------------------------------------------------
__global__ void __launch_bounds__(512) sample_kernel(float* __restrict__ out) {
    __shared__ float s_w[4][64];
    __shared__ int   s_base[4][64];
    __shared__ float val[2][64 * VST];     // ~35 KB

    int b   = blockIdx.y;
    int n0  = blockIdx.x << 6;
    int tid = threadIdx.x;
    int lane = tid & 31, w = tid >> 5;

    if (blockIdx.x == 0 && blockIdx.y == 0 && tid < 16)
        ((int*)g_bbox)[tid] = ((tid & 3) < 2) ? INT_MAX : INT_MIN;

    if (tid < 64) {
        int idx = b * NN + n0 + tid;
        int x0, x1, y0, y1; float wx, wy;
        point_coords(g_grid0[idx], g_grid1[idx], x0, x1, y0, y1, wx, wy);
        s_w[0][tid] = (1.0f - wy) * (1.0f - wx);
        s_w[1][tid] = (1.0f - wy) * wx;
        s_w[2][tid] = wy * (1.0f - wx);
        s_w[3][tid] = wy * wx;
        int r0 = (b * HH + y0) * WW;
        int r1 = (b * HH + y1) * WW;
        s_base[0][tid] = (r0 + x0) * C_ALL;
        s_base[1][tid] = (r0 + x1) * C_ALL;
        s_base[2][tid] = (r1 + x0) * C_ALL;
        s_base[3][tid] = (r1 + x1) * C_ALL;
    }
    __syncthreads();

    int p   = (w << 2) + (lane >> 3);   // this lane's point (0..63)
    int oct = lane & 7;                 // channel octet within 64-ch chunk
    int st_off = p * VST + (oct << 3) + ((oct >> 2) << 2);   // store base
    float pw[4];
    int   pb_[4];
#pragma unroll
    for (int t = 0; t < 4; t++) { pw[t] = s_w[t][p]; pb_[t] = s_base[t][p]; }

    auto gather = [&](int chunk, int buf) {
        int cc = chunk * 64 + (oct << 3);
        float r[8] = {0.f, 0.f, 0.f, 0.f, 0.f, 0.f, 0.f, 0.f};
#pragma unroll
        for (int t = 0; t < 4; t++) {
            uint4 u = *(const uint4*)&g_t[pb_[t] + cc];
            float wt = pw[t];
#pragma unroll
            for (int k = 0; k < 4; k++) {
                float2 f = __half22float2(((const __half2*)&u)[k]);
                r[2 * k]     += wt * f.x;
                r[2 * k + 1] += wt * f.y;
            }
        }
        float* vp = &val[buf][st_off];
#pragma unroll
        for (int k = 0; k < 8; k++) vp[k] = r[k];
    };

    gather(0, 0);
    __syncthreads();

    // load-side channel offset: c = 4w + j, octet offset = (c>>5)*4 = (w>>3)*4
    int ld_coff = (w << 2) + ((w >> 3) << 2);

#pragma unroll
    for (int chunk = 0; chunk < 7; chunk++) {
        int buf = chunk & 1;
        if (chunk + 1 < 7) gather(chunk + 1, buf ^ 1);

        int c0 = chunk * 64;
#pragma unroll
        for (int j = 0; j < 4; j++) {
            float* outp = out + ((size_t)(b * C_ALL + c0 + (w << 2) + j)) * NN + n0;
#pragma unroll
            for (int it = 0; it < 2; it++) {
                int n = it * 32 + lane;
                __stcs(&outp[n], val[buf][n * VST + ld_coff + j]);
            }
        }
        __syncthreads();
    }
}

// ---------------------------------------------------------------------------
extern "C" void kernel_launch(void* const* d_in, const int* in_sizes, int n_in,
                              void* d_out, int out_size) {
    const float* x_loc  = (const float*)d_in[0];
    const float* x_feat = (const float*)d_in[1];
    const float* m0     = (const float*)d_in[2];
    const float* m1     = (const float*)d_in[3];
    const float* m2     = (const float*)d_in[4];
    const float* W1     = (const float*)d_in[5];
    const float* b1     = (const float*)d_in[6];
    const float* W2     = (const float*)d_in[7];
    const float* b2     = (const float*)d_in[8];
    const float* Wr     = (const float*)d_in[9];
    const float* br     = (const float*)d_in[10];
    float* out = (float*)d_out;

    base_grid_kernel<<<512, 512>>>(x_loc, Wr, br);
    mlp_grid_kernel<<<512, 512>>>(x_loc, x_feat, W1, b1, W2, b2, Wr);
    transpose_kernel<<<dim3(4, 7, 256), 256>>>(m0, m1, m2);
    sample_kernel<<<dim3(NN / 64, BB), 512>>>(out);
}

// round 15
// speedup vs baseline: 1.1283x; 1.0466x over previous
#include <cuda_runtime.h>
#include <cuda_fp16.h>
#include <climits>

#define BB 4
#define NN 65536
#define HH 128
#define WW 128
#define C_ALL 448   // 64 + 128 + 256
#define CST 68      // staging: channel-major stride (68 mod 32 = 4 bank skew)

// fused NHWC fp16 scratch [b][y][x][448], 56 MB
__device__ __half g_t[(size_t)BB * HH * WW * C_ALL];
__device__ float  g_grid0[BB * NN];
__device__ float  g_grid1[BB * NN];
// bbox sentinels: statically initialized; re-armed by sample_kernel each run
// (sample never reads bbox, so the reset is safely ordered for the NEXT run).
__device__ int g_bbox[BB][4] = {
    {INT_MAX, INT_MAX, INT_MIN, INT_MIN}, {INT_MAX, INT_MAX, INT_MIN, INT_MIN},
    {INT_MAX, INT_MAX, INT_MIN, INT_MIN}, {INT_MAX, INT_MAX, INT_MIN, INT_MIN}};

// ---------------------------------------------------------------------------
__device__ __forceinline__ void point_coords(float gx, float gy,
                                             int& x0, int& x1, int& y0, int& y1,
                                             float& wx, float& wy) {
    float ix = ((gx + 1.0f) * 128.0f - 1.0f) * 0.5f;
    float iy = ((gy + 1.0f) * 128.0f - 1.0f) * 0.5f;
    ix = fminf(fmaxf(ix, 0.0f), 127.0f);
    iy = fminf(fmaxf(iy, 0.0f), 127.0f);
    float fx0 = floorf(ix), fy0 = floorf(iy);
    wx = ix - fx0; wy = iy - fy0;
    x0 = (int)fx0; y0 = (int)fy0;
    x1 = min(x0 + 1, 127); y1 = min(y0 + 1, 127);
}

// Block-wide bbox reduce; 512-thread block, all threads same batch b.
__device__ __forceinline__ void bbox_reduce(int b, int x0, int y0,
                                            int x1, int y1) {
    __shared__ int sm[4][16];
    int mnx = __reduce_min_sync(0xffffffffu, x0);
    int mny = __reduce_min_sync(0xffffffffu, y0);
    int mxx = __reduce_max_sync(0xffffffffu, x1);
    int mxy = __reduce_max_sync(0xffffffffu, y1);
    int w = threadIdx.x >> 5;
    if ((threadIdx.x & 31) == 0) {
        sm[0][w] = mnx; sm[1][w] = mny; sm[2][w] = mxx; sm[3][w] = mxy;
    }
    __syncthreads();
    if (threadIdx.x == 0) {
        int a0 = sm[0][0], a1 = sm[1][0], a2 = sm[2][0], a3 = sm[3][0];
#pragma unroll
        for (int i = 1; i < 16; i++) {
            a0 = min(a0, sm[0][i]); a1 = min(a1, sm[1][i]);
            a2 = max(a2, sm[2][i]); a3 = max(a3, sm[3][i]);
        }
        atomicMin(&g_bbox[b][0], a0); atomicMin(&g_bbox[b][1], a1);
        atomicMax(&g_bbox[b][2], a2); atomicMax(&g_bbox[b][3], a3);
    }
}

// ---------------------------------------------------------------------------
// Base grid + fused bbox. 512 blocks x 512 threads; block spans one batch.
// ---------------------------------------------------------------------------
__global__ void __launch_bounds__(512) base_grid_kernel(
        const float* __restrict__ x_loc, const float* __restrict__ Wr,
        const float* __restrict__ br) {
    int idx = blockIdx.x * 512 + threadIdx.x;
    int b = idx >> 16, n = idx & (NN - 1);
    float x0v = x_loc[(b * 3 + 0) * NN + n];
    float x1v = x_loc[(b * 3 + 1) * NN + n];
    float x2v = x_loc[(b * 3 + 2) * NN + n];
    float g0 = br[0] + Wr[0] * x0v + Wr[1] * x1v + Wr[2] * x2v;
    float g1 = br[1] + Wr[131] * x0v + Wr[132] * x1v + Wr[133] * x2v;
    g_grid0[idx] = g0;
    g_grid1[idx] = g1;
    int x0, x1, y0, y1; float wx, wy;
    point_coords(g0, g1, x0, x1, y0, y1, wx, wy);
    bbox_reduce(b, x0, y0, x1, y1);
}

// ---------------------------------------------------------------------------
// Fallback MLP path. Each block first checks (from L2) whether Wr touches
// the MLP features at all; early-exits when not (the benched case). When
// active it grows the bbox; bbox only accumulates so the union is safe.
// ---------------------------------------------------------------------------
__global__ void __launch_bounds__(512) mlp_grid_kernel(
        const float* __restrict__ x_loc, const float* __restrict__ x_feat,
        const float* __restrict__ W1, const float* __restrict__ b1,
        const float* __restrict__ W2, const float* __restrict__ b2,
        const float* __restrict__ Wr) {
    {
        int t = threadIdx.x, nz = 0;
        if (t < 262) {
            int row = t / 131, k = t % 131;
            if (k >= 3 && Wr[row * 131 + k] != 0.0f) nz = 1;
        }
        if (__syncthreads_or(nz) == 0) return;
    }
    int idx = blockIdx.x * 512 + threadIdx.x;
    int b = idx >> 16, n = idx & (NN - 1);

    float x[67];
    for (int k = 0; k < 3; k++)  x[k] = x_loc[(b * 3 + k) * NN + n];
    for (int k = 0; k < 64; k++) x[3 + k] = x_feat[(b * 64 + k) * NN + n];
    float h1[128];
    for (int j = 0; j < 128; j++) {
        float s = b1[j];
        for (int k = 0; k < 67; k++) s += W1[j * 67 + k] * x[k];
        h1[j] = fmaxf(s, 0.0f);
    }
    float g0 = 0.0f, g1 = 0.0f;
    for (int j = 0; j < 128; j++) {
        float s = b2[j];
        for (int k = 0; k < 128; k++) s += W2[j * 128 + k] * h1[k];
        s = fmaxf(s, 0.0f);
        g0 += Wr[3 + j] * s;
        g1 += Wr[131 + 3 + j] * s;
    }
    g0 += g_grid0[idx];
    g1 += g_grid1[idx];
    g_grid0[idx] = g0;
    g_grid1[idx] = g1;
    int x0, x1, y0, y1; float wx, wy;
    point_coords(g0, g1, x0, x1, y0, y1, wx, wy);
    bbox_reduce(b, x0, y0, x1, y1);
}

// ---------------------------------------------------------------------------
// bbox-gated transpose to flat NHWC fp16. grid (4, 7, 256), block = 256
// FLAT threads. TWO y rows, 32 x's, one 64-channel tile per block. Loads
// are 4x LDG.128 per thread; warp stores 64 contiguous fp16 (128 B)/texel.
// ---------------------------------------------------------------------------
__global__ void __launch_bounds__(256) transpose_kernel(
        const float* __restrict__ m0, const float* __restrict__ m1,
        const float* __restrict__ m2) {
    int b  = blockIdx.z >> 6;
    int yb = (blockIdx.z & 63) << 1;
    int xt = blockIdx.x << 5;
    int bx0 = g_bbox[b][0], bx1 = g_bbox[b][2];
    int by0 = g_bbox[b][1], by1 = g_bbox[b][3];
    if (yb + 1 < by0 || yb > by1 || xt > bx1 || xt + 31 < bx0) return;

    int ct = blockIdx.y;                   // 7 tiles of 64 channels
    const float* m; int C, c0, coff;
    if (ct == 0)      { m = m0; C = 64;  c0 = 0;             coff = 0; }
    else if (ct < 3)  { m = m1; C = 128; c0 = (ct - 1) * 64; coff = 64 + c0; }
    else              { m = m2; C = 256; c0 = (ct - 3) * 64; coff = 192 + c0; }

    __shared__ float tile[2][64][33];
    int tid = threadIdx.x;                 // FLAT 0..255
    // 1024 16B granules: g -> (q = x-quad, c, yy); consecutive tid = coalesced
#pragma unroll
    for (int i = 0; i < 4; i++) {
        int g = tid + i * 256;
        int q = g & 7, c = (g >> 3) & 63, yy = g >> 9;
        float4 v = *(const float4*)(m + ((size_t)(b * C + c0 + c) * HH + yb + yy) * WW + xt + q * 4);
        float* dst = &tile[yy][c][q * 4];
        dst[0] = v.x; dst[1] = v.y; dst[2] = v.z; dst[3] = v.w;
    }
    __syncthreads();

    // warp w handles x = xt + 4w .. 4w+3; lane = channel pair -> 128 B store
    int w = tid >> 5, lane = tid & 31;
#pragma unroll
    for (int yy = 0; yy < 2; yy++)
#pragma unroll
        for (int xi = 0; xi < 4; xi++) {
            int x = (w << 2) + xi;
            __half2 h = __floats2half2_rn(tile[yy][2 * lane][x], tile[yy][2 * lane + 1][x]);
            *(__half2*)&g_t[((size_t)((b * HH + yb + yy) * WW + xt + x)) * C_ALL + coff + 2 * lane] = h;
        }
}

// ---------------------------------------------------------------------------
// Bilinear gather + channel transpose. 64 points/block, 512 threads.
// Warp handles 4 points: lane>>3 = point-sub, lane&7 = channel octet.
// Gather: float4 (8 fp16) per texel row -> LDG.128, 512 B/warp; 8
// independent scalar STS (max ILP).
// Staging layout is CHANNEL-MAJOR with XOR swizzle:
//   value (c, n) at val[c*68 + (n ^ 4*(c>>3))]
//   stores: bank = 4k + 4((w&7)^oct) + s -> bijective over warp lanes
//   reads:  channel rows are n-contiguous (swizzle preserves 4-quads) ->
//           one LDS.128 + one STG.128 per 2 channel-halves (16 -> 4
//           instructions per thread per chunk on the write side).
// Double-buffered so gather(c+1) overlaps write(c). Block (0,0) re-arms
// bbox sentinels for the next replay.
// ---------------------------------------------------------------------------
__global__ void __launch_bounds__(512) sample_kernel(float* __restrict__ out) {
    __shared__ float s_w[4][64];
    __shared__ int   s_base[4][64];
    __shared__ float val[2][64 * CST];     // 34 KB

    int b   = blockIdx.y;
    int n0  = blockIdx.x << 6;
    int tid = threadIdx.x;
    int lane = tid & 31, w = tid >> 5;

    if (blockIdx.x == 0 && blockIdx.y == 0 && tid < 16)
        ((int*)g_bbox)[tid] = ((tid & 3) < 2) ? INT_MAX : INT_MIN;

    if (tid < 64) {
        int idx = b * NN + n0 + tid;
        int x0, x1, y0, y1; float wx, wy;
        point_coords(g_grid0[idx], g_grid1[idx], x0, x1, y0, y1, wx, wy);
        s_w[0][tid] = (1.0f - wy) * (1.0f - wx);
        s_w[1][tid] = (1.0f - wy) * wx;
        s_w[2][tid] = wy * (1.0f - wx);
        s_w[3][tid] = wy * wx;
        int r0 = (b * HH + y0) * WW;
        int r1 = (b * HH + y1) * WW;
        s_base[0][tid] = (r0 + x0) * C_ALL;
        s_base[1][tid] = (r0 + x1) * C_ALL;
        s_base[2][tid] = (r1 + x0) * C_ALL;
        s_base[3][tid] = (r1 + x1) * C_ALL;
    }
    __syncthreads();

    int p   = (w << 2) + (lane >> 3);   // this lane's point (0..63)
    int oct = lane & 7;                 // channel octet within 64-ch chunk
    // staging store base: channel row (oct*8), position p ^ 4*oct; +68 per k
    int st_off = (oct << 3) * CST + (p ^ (oct << 2));
    float pw[4];
    int   pb_[4];
#pragma unroll
    for (int t = 0; t < 4; t++) { pw[t] = s_w[t][p]; pb_[t] = s_base[t][p]; }

    auto gather = [&](int chunk, int buf) {
        int cc = chunk * 64 + (oct << 3);
        float r[8] = {0.f, 0.f, 0.f, 0.f, 0.f, 0.f, 0.f, 0.f};
#pragma unroll
        for (int t = 0; t < 4; t++) {
            uint4 u = *(const uint4*)&g_t[pb_[t] + cc];
            float wt = pw[t];
#pragma unroll
            for (int k = 0; k < 4; k++) {
                float2 f = __half22float2(((const __half2*)&u)[k]);
                r[2 * k]     += wt * f.x;
                r[2 * k + 1] += wt * f.y;
            }
        }
        float* vp = &val[buf][st_off];
#pragma unroll
        for (int k = 0; k < 8; k++) vp[k * CST] = r[k];
    };

    gather(0, 0);
    __syncthreads();

    // read-out mapping: half-warp j2 = lane>>4 -> channel 4w + 2i + j2;
    // n-quad qn = (lane&15)*4; swizzle const = 4*(w>>1) (4w..4w+3 share octet)
    int j2  = lane >> 4;
    int qn  = (lane & 15) << 2;
    int swz = (w >> 1) << 2;
    int qsw = qn ^ swz;

#pragma unroll
    for (int chunk = 0; chunk < 7; chunk++) {
        int buf = chunk & 1;
        if (chunk + 1 < 7) gather(chunk + 1, buf ^ 1);

        int c0 = chunk * 64;
#pragma unroll
        for (int i = 0; i < 2; i++) {
            int c = (w << 2) + (i << 1) + j2;      // channel within chunk
            float4 v = *(float4*)&val[buf][c * CST + qsw];
            float* outp = out + ((size_t)(b * C_ALL + c0 + c)) * NN + n0 + qn;
            __stcs((float4*)outp, v);
        }
        __syncthreads();
    }
}

// ---------------------------------------------------------------------------
extern "C" void kernel_launch(void* const* d_in, const int* in_sizes, int n_in,
                              void* d_out, int out_size) {
    const float* x_loc  = (const float*)d_in[0];
    const float* x_feat = (const float*)d_in[1];
    const float* m0     = (const float*)d_in[2];
    const float* m1     = (const float*)d_in[3];
    const float* m2     = (const float*)d_in[4];
    const float* W1     = (const float*)d_in[5];
    const float* b1     = (const float*)d_in[6];
    const float* W2     = (const float*)d_in[7];
    const float* b2     = (const float*)d_in[8];
    const float* Wr     = (const float*)d_in[9];
    const float* br     = (const float*)d_in[10];
    float* out = (float*)d_out;

    base_grid_kernel<<<512, 512>>>(x_loc, Wr, br);
    mlp_grid_kernel<<<512, 512>>>(x_loc, x_feat, W1, b1, W2, b2, Wr);
    transpose_kernel<<<dim3(4, 7, 256), 256>>>(m0, m1, m2);
    sample_kernel<<<dim3(NN / 64, BB), 512>>>(out);
}